// round 16
// baseline (speedup 1.0000x reference)
#include <cuda_runtime.h>
#include <stdint.h>

#define N_TOKENS 131072
#define D_MODEL  512
#define PATHS    16
#define CAP      16384                 // 2 * N / P
#define D4       (D_MODEL / 4)         // 128 float4 per row
#define ROWS     (PATHS * CAP)         // 262144 output rows

#define NB       128                   // route blocks (all co-resident: 1024thr, 2/SM)
#define TPB_R    1024                  // 32 warps, one token per thread
#define NWARP_R  32

// ---- scratch (no allocations allowed; zero-initialized at load) ----
__device__ int      g_cnt[PATHS];          // per-path count, clamped to CAP
__device__ int      g_slot[ROWS];          // slot -> token gather map
__device__ int      g_hist[PATHS * NB];    // per-(path, block) counts  [path][block]
__device__ unsigned g_arrive;              // grid barrier counter (self-resets)
__device__ unsigned g_done;                // completion counter (self-resets)

__device__ __forceinline__ unsigned vload(const unsigned* p) {
    return *(volatile const unsigned*)p;
}

// Route: argmax + per-warp hist + block scan -> publish hist -> resident-grid
// barrier (128 arrivals) -> bulk prefix per warp (128-entry rows) ->
// order-preserving positions -> slot map. PLC trigger fires right after the
// gather-visible writes (g_cnt, g_slot) are fenced; self-clean bookkeeping
// stays after the trigger, off the PLC critical path.
__global__ __launch_bounds__(TPB_R, 2) void k_route(const float* __restrict__ score) {
    __shared__ int sh_cnt[NWARP_R][PATHS];
    __shared__ int sh_wexcl[NWARP_R][PATHS];
    __shared__ int sh_excl[PATHS];
    __shared__ int sh_run[NWARP_R][PATHS];
    __shared__ int sh_last;
    const int tid = threadIdx.x, w = tid >> 5, lane = tid & 31, bid = blockIdx.x;
    const int tok = bid * TPB_R + tid;                  // one token per thread

    // ---- phase 1: argmax + per-warp per-path counts ----
    if (lane < PATHS) sh_cnt[w][lane] = 0;
    __syncwarp();
    int best;
    {
        const float4* sc = (const float4*)(score + (size_t)tok * PATHS);
        float4 a = __ldcs(sc), b = __ldcs(sc + 1), c = __ldcs(sc + 2), d = __ldcs(sc + 3);
        float v[16] = {a.x,a.y,a.z,a.w, b.x,b.y,b.z,b.w,
                       c.x,c.y,c.z,c.w, d.x,d.y,d.z,d.w};
        best = 0; float bv = v[0];
        #pragma unroll
        for (int p = 1; p < 16; p++) if (v[p] > bv) { bv = v[p]; best = p; }  // first-max
        unsigned m = __match_any_sync(0xffffffffu, best);
        if ((__ffs(m) - 1) == lane) sh_cnt[w][best] += __popc(m);
    }
    __syncthreads();

    // ---- block scan over 32 warps + publish block aggregate ----
    if (w == 0 && lane < PATHS) {
        int run = 0;
        #pragma unroll
        for (int ww = 0; ww < NWARP_R; ww++) { int v = sh_cnt[ww][lane]; sh_wexcl[ww][lane] = run; run += v; }
        g_hist[lane * NB + bid] = run;                  // [path][block]
        __threadfence();
    }
    __syncthreads();

    // ---- resident-grid barrier (all NB blocks co-resident by construction) ----
    if (tid == 0) {
        atomicAdd(&g_arrive, 1u);
        while (vload(&g_arrive) < (unsigned)NB) { }
    }
    __syncthreads();

    // ---- bulk prefix: warp w (< PATHS) owns path w; read full hist row ----
    if (w < PATHS) {
        int excl = 0, tot = 0;
        #pragma unroll
        for (int s = 0; s < NB / 32; s++) {
            const int j = s * 32 + lane;
            const int v = g_hist[w * NB + j];
            tot += v;
            if (j < bid) excl += v;
        }
        excl = __reduce_add_sync(0xffffffffu, excl);
        tot  = __reduce_add_sync(0xffffffffu, tot);
        if (lane == 0) {
            sh_excl[w] = excl;
            if (bid == 0) g_cnt[w] = tot < CAP ? tot : CAP;
        }
    }
    __syncthreads();

    // ---- order-preserving rank -> slot map ----
    if (lane < PATHS) sh_run[w][lane] = sh_excl[lane] + sh_wexcl[w][lane];
    __syncwarp();
    {
        unsigned m = __match_any_sync(0xffffffffu, best);
        const int rank = __popc(m & ((1u << lane) - 1u));
        const int pos = sh_run[w][best] + rank;
        if (pos < CAP) g_slot[best * CAP + pos] = tok;
    }

    // ---- all gather-visible writes (g_cnt, g_slot) done: fence, then trigger ----
    __threadfence();
    __syncthreads();
#if __CUDA_ARCH__ >= 900
    cudaTriggerProgrammaticLaunchCompletion();
#endif

    // ---- self-clean (next-replay state only; gather never reads these) ----
    if (tid == 0) sh_last = (atomicAdd(&g_done, 1u) == (unsigned)(NB - 1));
    __syncthreads();
    if (sh_last && tid == 0) { g_arrive = 0; g_done = 0; }
}

// Gather: one warp per output row, 4 independent float4s per lane (MLP=4).
// Measured optimum: 512 thr, 16384 blocks, regs 26, ~6.3 TB/s.
#define GROWS_PB 16
__global__ __launch_bounds__(512) void k_gather(const float4* __restrict__ in4,
                                                float4* __restrict__ out4) {
#if __CUDA_ARCH__ >= 900
    cudaGridDependencySynchronize();                    // PDL: wait for k_route
#endif
    const int w = threadIdx.x >> 5, lane = threadIdx.x & 31;
    const int r = blockIdx.x * GROWS_PB + w;            // output row in [0, ROWS)
    const int p = r >> 14;                              // r / CAP
    const int j = r & (CAP - 1);                        // r % CAP
    float4 v0 = make_float4(0.f,0.f,0.f,0.f);
    float4 v1 = v0, v2 = v0, v3 = v0;
    if (j < g_cnt[p]) {
        const float4* src = in4 + (size_t)g_slot[r] * D4 + lane;
        v0 = src[0];
        v1 = src[32];
        v2 = src[64];
        v3 = src[96];
    }
    float4* dst = out4 + (size_t)r * D4 + lane;
    dst[0]  = v0;
    dst[32] = v1;
    dst[64] = v2;
    dst[96] = v3;
}

extern "C" void kernel_launch(void* const* d_in, const int* in_sizes, int n_in,
                              void* d_out, int out_size) {
    const float* inputs = (const float*)d_in[0];
    const float* score  = (const float*)d_in[1];
    if (in_sizes[0] == N_TOKENS * PATHS) {   // defensive: identify by element count
        inputs = (const float*)d_in[1];
        score  = (const float*)d_in[0];
    }
    k_route<<<NB, TPB_R>>>(score);

    cudaLaunchConfig_t cfg = {};
    cfg.gridDim  = dim3(ROWS / GROWS_PB, 1, 1);
    cfg.blockDim = dim3(512, 1, 1);
    cfg.stream   = 0;
    cudaLaunchAttribute attr[1];
    attr[0].id = cudaLaunchAttributeProgrammaticStreamSerialization;
    attr[0].val.programmaticStreamSerializationAllowed = 1;
    cfg.attrs = attr;
    cfg.numAttrs = 1;
    cudaLaunchKernelEx(&cfg, k_gather, (const float4*)inputs, (float4*)d_out);
}

// round 17
// speedup vs baseline: 1.0017x; 1.0017x over previous
#include <cuda_runtime.h>
#include <stdint.h>

#define N_TOKENS 131072
#define D_MODEL  512
#define PATHS    16
#define CAP      16384                 // 2 * N / P
#define D4       (D_MODEL / 4)         // 128 float4 per row
#define ROWS     (PATHS * CAP)         // 262144 output rows

#define NB       256                   // route blocks (all co-resident: 512thr)
#define TPB      512                   // 16 warps, one token per thread
#define NWARP    16

// ---- scratch (no allocations allowed; zero-initialized at load) ----
__device__ int      g_cnt[PATHS];          // per-path count, clamped to CAP
__device__ int      g_slot[ROWS];          // slot -> token gather map
__device__ int      g_hist[PATHS * NB];    // per-(path, block) counts  [path][block]
__device__ unsigned g_arrive;              // grid barrier counter (self-resets)
__device__ unsigned g_done;                // completion counter (self-resets)

__device__ __forceinline__ unsigned vload(const unsigned* p) {
    return *(volatile const unsigned*)p;
}

// Route: argmax + per-warp hist + block scan -> publish hist -> resident-grid
// barrier -> bulk prefix per warp -> order-preserving positions -> slot map.
// PLC trigger fires right after this block's gather-visible writes are fenced
// (g_cnt + g_slot); self-clean bookkeeping (never read by the gather) stays
// after the trigger, off the PLC critical path.
__global__ __launch_bounds__(TPB, 4) void k_route(const float* __restrict__ score) {
    __shared__ int sh_cnt[NWARP][PATHS];
    __shared__ int sh_wexcl[NWARP][PATHS];
    __shared__ int sh_excl[PATHS];
    __shared__ int sh_run[NWARP][PATHS];
    __shared__ int sh_last;
    const int tid = threadIdx.x, w = tid >> 5, lane = tid & 31, bid = blockIdx.x;
    const int tok = bid * TPB + tid;                    // one token per thread

    // ---- phase 1: argmax + per-warp per-path counts ----
    if (lane < PATHS) sh_cnt[w][lane] = 0;
    __syncwarp();
    int best;
    {
        const float4* sc = (const float4*)(score + (size_t)tok * PATHS);
        float4 a = __ldcs(sc), b = __ldcs(sc + 1), c = __ldcs(sc + 2), d = __ldcs(sc + 3);
        float v[16] = {a.x,a.y,a.z,a.w, b.x,b.y,b.z,b.w,
                       c.x,c.y,c.z,c.w, d.x,d.y,d.z,d.w};
        best = 0; float bv = v[0];
        #pragma unroll
        for (int p = 1; p < 16; p++) if (v[p] > bv) { bv = v[p]; best = p; }  // first-max
        unsigned m = __match_any_sync(0xffffffffu, best);
        if ((__ffs(m) - 1) == lane) sh_cnt[w][best] += __popc(m);
    }
    __syncthreads();

    // ---- block scan over 16 warps + publish block aggregate ----
    if (w == 0 && lane < PATHS) {
        int run = 0;
        #pragma unroll
        for (int ww = 0; ww < NWARP; ww++) { int v = sh_cnt[ww][lane]; sh_wexcl[ww][lane] = run; run += v; }
        g_hist[lane * NB + bid] = run;                  // [path][block]
        __threadfence();
    }
    __syncthreads();

    // ---- resident-grid barrier (all NB blocks co-resident by construction) ----
    if (tid == 0) {
        atomicAdd(&g_arrive, 1u);
        while (vload(&g_arrive) < (unsigned)NB) { }
    }
    __syncthreads();

    // ---- bulk prefix: warp w owns path w; read full hist row from L2 ----
    {
        int excl = 0, tot = 0;
        #pragma unroll
        for (int s = 0; s < NB / 32; s++) {
            const int j = s * 32 + lane;
            const int v = g_hist[w * NB + j];
            tot += v;
            if (j < bid) excl += v;
        }
        excl = __reduce_add_sync(0xffffffffu, excl);
        tot  = __reduce_add_sync(0xffffffffu, tot);
        if (lane == 0) {
            sh_excl[w] = excl;
            if (bid == 0) g_cnt[w] = tot < CAP ? tot : CAP;
        }
    }
    __syncthreads();

    // ---- order-preserving rank -> slot map ----
    if (lane < PATHS) sh_run[w][lane] = sh_excl[lane] + sh_wexcl[w][lane];
    __syncwarp();
    {
        unsigned m = __match_any_sync(0xffffffffu, best);
        const int rank = __popc(m & ((1u << lane) - 1u));
        const int pos = sh_run[w][best] + rank;
        if (pos < CAP) g_slot[best * CAP + pos] = tok;
    }

    // ---- all gather-visible writes (g_cnt, g_slot) done: fence, then trigger ----
    __threadfence();
    __syncthreads();
#if __CUDA_ARCH__ >= 900
    cudaTriggerProgrammaticLaunchCompletion();
#endif

    // ---- self-clean (next-replay state only; gather never reads these) ----
    if (tid == 0) sh_last = (atomicAdd(&g_done, 1u) == (unsigned)(NB - 1));
    __syncthreads();
    if (sh_last && tid == 0) { g_arrive = 0; g_done = 0; }
}

// Gather: one warp per output row, 4 independent float4s per lane (MLP=4).
// Measured optimum: 512 thr, 16384 blocks, regs 26, ~6.3 TB/s (chip ceiling).
#define GROWS_PB 16
__global__ __launch_bounds__(512) void k_gather(const float4* __restrict__ in4,
                                                float4* __restrict__ out4) {
#if __CUDA_ARCH__ >= 900
    cudaGridDependencySynchronize();                    // PDL: wait for k_route
#endif
    const int w = threadIdx.x >> 5, lane = threadIdx.x & 31;
    const int r = blockIdx.x * GROWS_PB + w;            // output row in [0, ROWS)
    const int p = r >> 14;                              // r / CAP
    const int j = r & (CAP - 1);                        // r % CAP
    float4 v0 = make_float4(0.f,0.f,0.f,0.f);
    float4 v1 = v0, v2 = v0, v3 = v0;
    if (j < g_cnt[p]) {
        const float4* src = in4 + (size_t)g_slot[r] * D4 + lane;
        v0 = src[0];
        v1 = src[32];
        v2 = src[64];
        v3 = src[96];
    }
    float4* dst = out4 + (size_t)r * D4 + lane;
    dst[0]  = v0;
    dst[32] = v1;
    dst[64] = v2;
    dst[96] = v3;
}

extern "C" void kernel_launch(void* const* d_in, const int* in_sizes, int n_in,
                              void* d_out, int out_size) {
    const float* inputs = (const float*)d_in[0];
    const float* score  = (const float*)d_in[1];
    if (in_sizes[0] == N_TOKENS * PATHS) {   // defensive: identify by element count
        inputs = (const float*)d_in[1];
        score  = (const float*)d_in[0];
    }
    k_route<<<NB, TPB>>>(score);

    cudaLaunchConfig_t cfg = {};
    cfg.gridDim  = dim3(ROWS / GROWS_PB, 1, 1);
    cfg.blockDim = dim3(512, 1, 1);
    cfg.stream   = 0;
    cudaLaunchAttribute attr[1];
    attr[0].id = cudaLaunchAttributeProgrammaticStreamSerialization;
    attr[0].val.programmaticStreamSerializationAllowed = 1;
    cfg.attrs = attr;
    cfg.numAttrs = 1;
    cudaLaunchKernelEx(&cfg, k_gather, (const float4*)inputs, (float4*)d_out);
}